// round 1
// baseline (speedup 1.0000x reference)
#include <cuda_runtime.h>
#include <math.h>

#define D_MODEL 1024
#define NUM_HEAD 16
#define HEAD_DIM 64
#define BATCH 2
#define SEQ 2048
#define MTOT (BATCH * SEQ)   // 4096

// Scratch (static device globals: allowed under alloc guards)
__device__ float g_Q[(size_t)MTOT * D_MODEL];
__device__ float g_K[(size_t)MTOT * D_MODEL];
__device__ float g_V[(size_t)MTOT * D_MODEL];
__device__ float g_O[(size_t)MTOT * D_MODEL];

// ---------------------------------------------------------------------------
// SGEMM (NT): C[M,N] = A[M,K] @ W[N,K]^T + bias[N]
// 128x128 tile, BK=8, 8x8 per-thread microtile, 256 threads.
// ---------------------------------------------------------------------------
#define BM 128
#define BN 128
#define BKD 8
#define TM 8
#define TN 8

__global__ __launch_bounds__(256) void sgemm_nt_bias(
    const float* __restrict__ A, const float* __restrict__ W,
    const float* __restrict__ bias, float* __restrict__ C,
    int M, int N, int K)
{
    __shared__ float As[BKD][BM];
    __shared__ float Bs[BKD][BN];

    const int tid = threadIdx.x;
    const int tx = tid & 15;    // 0..15 (N direction)
    const int ty = tid >> 4;    // 0..15 (M direction)

    const float* Ab = A + (size_t)blockIdx.y * BM * K;
    const float* Wb = W + (size_t)blockIdx.x * BN * K;

    float acc[TM][TN];
#pragma unroll
    for (int i = 0; i < TM; i++)
#pragma unroll
        for (int j = 0; j < TN; j++) acc[i][j] = 0.0f;

    const int lrow = tid >> 1;        // 0..127
    const int lcol = (tid & 1) * 4;   // 0 or 4

    for (int k0 = 0; k0 < K; k0 += BKD) {
        float4 av = *(const float4*)(Ab + (size_t)lrow * K + k0 + lcol);
        float4 wv = *(const float4*)(Wb + (size_t)lrow * K + k0 + lcol);
        As[lcol + 0][lrow] = av.x; As[lcol + 1][lrow] = av.y;
        As[lcol + 2][lrow] = av.z; As[lcol + 3][lrow] = av.w;
        Bs[lcol + 0][lrow] = wv.x; Bs[lcol + 1][lrow] = wv.y;
        Bs[lcol + 2][lrow] = wv.z; Bs[lcol + 3][lrow] = wv.w;
        __syncthreads();

#pragma unroll
        for (int k = 0; k < BKD; k++) {
            float ar[TM], br[TN];
            *(float4*)&ar[0] = *(const float4*)&As[k][ty * TM];
            *(float4*)&ar[4] = *(const float4*)&As[k][ty * TM + 4];
            *(float4*)&br[0] = *(const float4*)&Bs[k][tx * TN];
            *(float4*)&br[4] = *(const float4*)&Bs[k][tx * TN + 4];
#pragma unroll
            for (int i = 0; i < TM; i++)
#pragma unroll
                for (int j = 0; j < TN; j++)
                    acc[i][j] = fmaf(ar[i], br[j], acc[i][j]);
        }
        __syncthreads();
    }

    const int coln = blockIdx.x * BN + tx * TN;
    float bv[TN];
    *(float4*)&bv[0] = *(const float4*)(bias + coln);
    *(float4*)&bv[4] = *(const float4*)(bias + coln + 4);

#pragma unroll
    for (int i = 0; i < TM; i++) {
        const int row = blockIdx.y * BM + ty * TM + i;
        float4 o0 = make_float4(acc[i][0] + bv[0], acc[i][1] + bv[1],
                                acc[i][2] + bv[2], acc[i][3] + bv[3]);
        float4 o1 = make_float4(acc[i][4] + bv[4], acc[i][5] + bv[5],
                                acc[i][6] + bv[6], acc[i][7] + bv[7]);
        *(float4*)(C + (size_t)row * N + coln)     = o0;
        *(float4*)(C + (size_t)row * N + coln + 4) = o1;
    }
}

// ---------------------------------------------------------------------------
// Flash attention, fp32, non-causal. One block per (b,h,q-tile of 64).
// 256 threads, 16x16 layout, 4x4 microtiles for both S and O.
// Smem: Qt[hd][q] + Kt[hd][k] (reused as P[q][k]) + Vs[k][hd] = 48 KB exactly.
// ---------------------------------------------------------------------------
#define BQ 64
#define BKT 64

__global__ __launch_bounds__(256) void flash_attn(
    const float* __restrict__ Qg, const float* __restrict__ Kg,
    const float* __restrict__ Vg, float* __restrict__ Og)
{
    __shared__ float Qt[HEAD_DIM][BQ];    // transposed: [hd][q]
    __shared__ float KtP[HEAD_DIM][BKT];  // K transposed [hd][k]; reused as P[q][k]
    __shared__ float Vs[BKT][HEAD_DIM];   // [k][hd]

    const int tid = threadIdx.x;
    const int tx = tid & 15;   // 0..15
    const int ty = tid >> 4;   // 0..15
    const int bh = blockIdx.y;
    const int b = bh >> 4;
    const int h = bh & 15;
    const int q0 = blockIdx.x * BQ;

    const float* Qbase = Qg + ((size_t)(b * SEQ + q0) * D_MODEL) + h * HEAD_DIM;
    const float* Kbase = Kg + ((size_t)(b * SEQ) * D_MODEL) + h * HEAD_DIM;
    const float* Vbase = Vg + ((size_t)(b * SEQ) * D_MODEL) + h * HEAD_DIM;

    const int lr = tid >> 4;          // 0..15
    const int lc = (tid & 15) * 4;    // 0..60

    // Load Q tile transposed (once)
#pragma unroll
    for (int it = 0; it < 4; it++) {
        const int q = lr + it * 16;
        float4 v = *(const float4*)(Qbase + (size_t)q * D_MODEL + lc);
        Qt[lc + 0][q] = v.x; Qt[lc + 1][q] = v.y;
        Qt[lc + 2][q] = v.z; Qt[lc + 3][q] = v.w;
    }

    float m_i[4], l_i[4], acc[4][4];
#pragma unroll
    for (int i = 0; i < 4; i++) {
        m_i[i] = -1e30f;
        l_i[i] = 0.0f;
#pragma unroll
        for (int j = 0; j < 4; j++) acc[i][j] = 0.0f;
    }

    const float scale = 0.125f;  // 1/sqrt(64)

    for (int kt = 0; kt < SEQ; kt += BKT) {
        __syncthreads();  // prior PV reads of KtP/Vs done; also covers Qt on iter 0

        // Load K tile transposed + V tile direct
#pragma unroll
        for (int it = 0; it < 4; it++) {
            const int kk = lr + it * 16;
            float4 kv = *(const float4*)(Kbase + (size_t)(kt + kk) * D_MODEL + lc);
            KtP[lc + 0][kk] = kv.x; KtP[lc + 1][kk] = kv.y;
            KtP[lc + 2][kk] = kv.z; KtP[lc + 3][kk] = kv.w;
            float4 vv = *(const float4*)(Vbase + (size_t)(kt + kk) * D_MODEL + lc);
            *(float4*)&Vs[kk][lc] = vv;
        }
        __syncthreads();

        // S[q][k] = sum_d Qt[d][q] * Kt[d][k]
        float s[4][4];
#pragma unroll
        for (int i = 0; i < 4; i++)
#pragma unroll
            for (int j = 0; j < 4; j++) s[i][j] = 0.0f;

#pragma unroll
        for (int k = 0; k < HEAD_DIM; k++) {
            float ar[4], br[4];
            *(float4*)&ar[0] = *(const float4*)&Qt[k][ty * 4];
            *(float4*)&br[0] = *(const float4*)&KtP[k][tx * 4];
#pragma unroll
            for (int i = 0; i < 4; i++)
#pragma unroll
                for (int j = 0; j < 4; j++)
                    s[i][j] = fmaf(ar[i], br[j], s[i][j]);
        }

        // Online softmax per row group (16 lanes share each row group)
        float mnew[4], corr[4], rsum[4];
#pragma unroll
        for (int i = 0; i < 4; i++) {
            float tmax = -1e30f;
#pragma unroll
            for (int j = 0; j < 4; j++) {
                s[i][j] *= scale;
                tmax = fmaxf(tmax, s[i][j]);
            }
#pragma unroll
            for (int off = 1; off < 16; off <<= 1)
                tmax = fmaxf(tmax, __shfl_xor_sync(0xffffffffu, tmax, off, 16));
            mnew[i] = fmaxf(m_i[i], tmax);
            corr[i] = __expf(m_i[i] - mnew[i]);
            float rs = 0.0f;
#pragma unroll
            for (int j = 0; j < 4; j++) {
                s[i][j] = __expf(s[i][j] - mnew[i]);
                rs += s[i][j];
            }
#pragma unroll
            for (int off = 1; off < 16; off <<= 1)
                rs += __shfl_xor_sync(0xffffffffu, rs, off, 16);
            rsum[i] = rs;
        }
#pragma unroll
        for (int i = 0; i < 4; i++) {
            l_i[i] = l_i[i] * corr[i] + rsum[i];
            m_i[i] = mnew[i];
#pragma unroll
            for (int j = 0; j < 4; j++) acc[i][j] *= corr[i];
        }

        __syncthreads();  // all reads of KtP-as-K done
        // Write P into KtP reinterpreted as P[q][k]
        float* Pf = (float*)KtP;
#pragma unroll
        for (int i = 0; i < 4; i++) {
            *(float4*)&Pf[(ty * 4 + i) * BKT + tx * 4] =
                make_float4(s[i][0], s[i][1], s[i][2], s[i][3]);
        }
        __syncthreads();

        // O[q][d] += P[q][k] * V[k][d]
#pragma unroll
        for (int k4 = 0; k4 < BKT; k4 += 4) {
            float pr[4][4];
#pragma unroll
            for (int i = 0; i < 4; i++)
                *(float4*)&pr[i][0] = *(const float4*)&Pf[(ty * 4 + i) * BKT + k4];
#pragma unroll
            for (int kk = 0; kk < 4; kk++) {
                float vr[4];
                *(float4*)&vr[0] = *(const float4*)&Vs[k4 + kk][tx * 4];
#pragma unroll
                for (int i = 0; i < 4; i++)
#pragma unroll
                    for (int j = 0; j < 4; j++)
                        acc[i][j] = fmaf(pr[i][kk], vr[j], acc[i][j]);
            }
        }
    }

    // Final normalize + write
#pragma unroll
    for (int i = 0; i < 4; i++) {
        const float inv = 1.0f / l_i[i];
        const int q = q0 + ty * 4 + i;
        float4 o = make_float4(acc[i][0] * inv, acc[i][1] * inv,
                               acc[i][2] * inv, acc[i][3] * inv);
        *(float4*)(Og + ((size_t)(b * SEQ + q) * D_MODEL) + h * HEAD_DIM + tx * 4) = o;
    }
}

// ---------------------------------------------------------------------------
// Launch
// ---------------------------------------------------------------------------
extern "C" void kernel_launch(void* const* d_in, const int* in_sizes, int n_in,
                              void* d_out, int out_size)
{
    const float* x  = (const float*)d_in[0];
    const float* Wq = (const float*)d_in[1];
    const float* bq = (const float*)d_in[2];
    const float* Wk = (const float*)d_in[3];
    const float* bk = (const float*)d_in[4];
    const float* Wv = (const float*)d_in[5];
    const float* bv = (const float*)d_in[6];
    const float* Wo = (const float*)d_in[7];
    const float* bo = (const float*)d_in[8];
    float* out = (float*)d_out;

    float *Qd, *Kd, *Vd, *Od;
    cudaGetSymbolAddress((void**)&Qd, g_Q);
    cudaGetSymbolAddress((void**)&Kd, g_K);
    cudaGetSymbolAddress((void**)&Vd, g_V);
    cudaGetSymbolAddress((void**)&Od, g_O);

    dim3 gemm_grid(D_MODEL / BN, MTOT / BM);  // (8, 32)
    sgemm_nt_bias<<<gemm_grid, 256>>>(x, Wq, bq, Qd, MTOT, D_MODEL, D_MODEL);
    sgemm_nt_bias<<<gemm_grid, 256>>>(x, Wk, bk, Kd, MTOT, D_MODEL, D_MODEL);
    sgemm_nt_bias<<<gemm_grid, 256>>>(x, Wv, bv, Vd, MTOT, D_MODEL, D_MODEL);

    dim3 attn_grid(SEQ / BQ, BATCH * NUM_HEAD);  // (32, 32)
    flash_attn<<<attn_grid, 256>>>(Qd, Kd, Vd, Od);

    sgemm_nt_bias<<<gemm_grid, 256>>>(Od, Wo, bo, out, MTOT, D_MODEL, D_MODEL);
}

// round 2
// speedup vs baseline: 2.0032x; 2.0032x over previous
#include <cuda_runtime.h>
#include <math.h>
#include <stdint.h>

#define D_MODEL 1024
#define NUM_HEAD 16
#define HEAD_DIM 64
#define BATCH 2
#define SEQ 2048
#define MTOT 4096

// Scratch
__device__ float g_Q[(size_t)MTOT * D_MODEL];
__device__ float g_K[(size_t)MTOT * D_MODEL];
__device__ float g_V[(size_t)MTOT * D_MODEL];
__device__ float g_O[(size_t)MTOT * D_MODEL];

__device__ __forceinline__ uint32_t f2tf(float x) {
    uint32_t r;
    asm("cvt.rna.tf32.f32 %0, %1;" : "=r"(r) : "f"(x));
    return r;
}

__device__ __forceinline__ void mma_m16n8k8(float d[4], const uint32_t a[4],
                                            const uint32_t b[2], const float c[4]) {
    asm volatile(
        "mma.sync.aligned.m16n8k8.row.col.f32.tf32.tf32.f32 "
        "{%0,%1,%2,%3}, {%4,%5,%6,%7}, {%8,%9}, {%10,%11,%12,%13};\n"
        : "=f"(d[0]), "=f"(d[1]), "=f"(d[2]), "=f"(d[3])
        : "r"(a[0]), "r"(a[1]), "r"(a[2]), "r"(a[3]),
          "r"(b[0]), "r"(b[1]),
          "f"(c[0]), "f"(c[1]), "f"(c[2]), "f"(c[3]));
}

// ---------------------------------------------------------------------------
// GEMM (NT): C[M,N] = A[M,K] @ W[N,K]^T + bias.  M=4096,N=1024,K=1024.
// BM=BN=128, BK=32. 256 threads = 8 warps (4x2), warp tile 32x64.
// Smem layout: T[k][x] at word  k*128 + (x ^ (8*(k&3)))  -> conflict-free
// for both tile-store and fragment loads.
// ---------------------------------------------------------------------------
__global__ __launch_bounds__(256) void gemm_tf32(
    const float* __restrict__ A, const float* __restrict__ W,
    const float* __restrict__ bias, float* __restrict__ C)
{
    const int K = D_MODEL;
    __shared__ uint32_t As[32 * 128];
    __shared__ uint32_t Bs[32 * 128];

    const int tid = threadIdx.x;
    const int warp = tid >> 5, lane = tid & 31;
    const int wm = warp >> 1, wn = warp & 1;
    const int tm = lane >> 2, tk = lane & 3;

    const float* Ab = A + (size_t)(blockIdx.y * 128) * K;
    const float* Wb = W + (size_t)(blockIdx.x * 128) * K;

    // loader: thread covers rows {lrow, lrow+64}, k-chunk of 8 at lkc
    const int lrow = lane + ((warp >> 2) << 5);  // 0..63
    const int lkc = (warp & 3) * 8;              // 0,8,16,24

    float c[2][8][4];
#pragma unroll
    for (int mt = 0; mt < 2; mt++)
#pragma unroll
        for (int nt = 0; nt < 8; nt++)
#pragma unroll
            for (int i = 0; i < 4; i++) c[mt][nt][i] = 0.0f;

    float4 pa[4], pb[4];

    // prefetch k0 = 0
#pragma unroll
    for (int i = 0; i < 2; i++) {
        const size_t ro = (size_t)(lrow + 64 * i) * K + lkc;
        pa[i * 2 + 0] = *(const float4*)(Ab + ro);
        pa[i * 2 + 1] = *(const float4*)(Ab + ro + 4);
        pb[i * 2 + 0] = *(const float4*)(Wb + ro);
        pb[i * 2 + 1] = *(const float4*)(Wb + ro + 4);
    }

    for (int k0 = 0; k0 < K; k0 += 32) {
        // store prefetched tile (conflict-free scatter)
#pragma unroll
        for (int i = 0; i < 2; i++) {
            const int r = lrow + 64 * i;
            float va[8] = {pa[i*2].x, pa[i*2].y, pa[i*2].z, pa[i*2].w,
                           pa[i*2+1].x, pa[i*2+1].y, pa[i*2+1].z, pa[i*2+1].w};
            float vb[8] = {pb[i*2].x, pb[i*2].y, pb[i*2].z, pb[i*2].w,
                           pb[i*2+1].x, pb[i*2+1].y, pb[i*2+1].z, pb[i*2+1].w};
#pragma unroll
            for (int c4 = 0; c4 < 8; c4++) {
                const int kk = lkc + c4;
                As[kk * 128 + (r ^ ((c4 & 3) << 3))] = f2tf(va[c4]);
                Bs[kk * 128 + (r ^ ((c4 & 3) << 3))] = f2tf(vb[c4]);
            }
        }
        __syncthreads();

        if (k0 + 32 < K) {
#pragma unroll
            for (int i = 0; i < 2; i++) {
                const size_t ro = (size_t)(lrow + 64 * i) * K + k0 + 32 + lkc;
                pa[i * 2 + 0] = *(const float4*)(Ab + ro);
                pa[i * 2 + 1] = *(const float4*)(Ab + ro + 4);
                pb[i * 2 + 0] = *(const float4*)(Wb + ro);
                pb[i * 2 + 1] = *(const float4*)(Wb + ro + 4);
            }
        }

#pragma unroll
        for (int ks = 0; ks < 4; ks++) {
            const int kb = ks * 8;
            uint32_t af[2][4], bf[8][2];
#pragma unroll
            for (int mt = 0; mt < 2; mt++) {
                const int m0 = wm * 32 + mt * 16;
                af[mt][0] = As[(kb + tk) * 128 + ((m0 + tm) ^ (tk << 3))];
                af[mt][1] = As[(kb + tk) * 128 + ((m0 + tm + 8) ^ (tk << 3))];
                af[mt][2] = As[(kb + tk + 4) * 128 + ((m0 + tm) ^ (tk << 3))];
                af[mt][3] = As[(kb + tk + 4) * 128 + ((m0 + tm + 8) ^ (tk << 3))];
            }
#pragma unroll
            for (int nt = 0; nt < 8; nt++) {
                const int n0 = wn * 64 + nt * 8;
                bf[nt][0] = Bs[(kb + tk) * 128 + ((n0 + tm) ^ (tk << 3))];
                bf[nt][1] = Bs[(kb + tk + 4) * 128 + ((n0 + tm) ^ (tk << 3))];
            }
#pragma unroll
            for (int mt = 0; mt < 2; mt++)
#pragma unroll
                for (int nt = 0; nt < 8; nt++)
                    mma_m16n8k8(c[mt][nt], af[mt], bf[nt], c[mt][nt]);
        }
        __syncthreads();
    }

    // epilogue: bias + store
#pragma unroll
    for (int mt = 0; mt < 2; mt++) {
        const int r0 = blockIdx.y * 128 + wm * 32 + mt * 16 + tm;
#pragma unroll
        for (int nt = 0; nt < 8; nt++) {
            const int col = blockIdx.x * 128 + wn * 64 + nt * 8 + 2 * tk;
            const float b0 = bias[col], b1 = bias[col + 1];
            *(float2*)(C + (size_t)r0 * D_MODEL + col) =
                make_float2(c[mt][nt][0] + b0, c[mt][nt][1] + b1);
            *(float2*)(C + (size_t)(r0 + 8) * D_MODEL + col) =
                make_float2(c[mt][nt][2] + b0, c[mt][nt][3] + b1);
        }
    }
}

// ---------------------------------------------------------------------------
// Flash attention, tf32 mma. 4 warps (128 thr). BQ=128 (32 q-rows/warp,
// 2 m-tiles), BKT=64. Smem (dynamic, 96KB): Qs[64k][128m], Ks[64k][64n],
// Vs[64k][64n], Ps[64k][128m]; all XOR-swizzled as in the GEMM.
// ---------------------------------------------------------------------------
__global__ __launch_bounds__(128) void flash_tf32(
    const float* __restrict__ Qg, const float* __restrict__ Kg,
    const float* __restrict__ Vg, float* __restrict__ Og)
{
    extern __shared__ uint32_t sm[];
    uint32_t* Qs = sm;            // 64*128
    uint32_t* Ks = sm + 8192;     // 64*64
    uint32_t* Vs = sm + 12288;    // 64*64
    uint32_t* Ps = sm + 16384;    // 64*128

    const int tid = threadIdx.x;
    const int warp = tid >> 5, lane = tid & 31;
    const int tm = lane >> 2, tk = lane & 3;
    const int b = blockIdx.y >> 4, h = blockIdx.y & 15;
    const int q0 = blockIdx.x * 128;

    const float* Qb = Qg + (size_t)(b * SEQ + q0) * D_MODEL + h * HEAD_DIM;
    const float* Kb = Kg + (size_t)(b * SEQ) * D_MODEL + h * HEAD_DIM;
    const float* Vb = Vg + (size_t)(b * SEQ) * D_MODEL + h * HEAD_DIM;

    const int rr = lane + ((warp & 1) << 5);  // 0..63
    const int cc = (warp >> 1) << 5;          // 0 or 32

    // Load Q tile: 128 rows x 64 cols
#pragma unroll
    for (int j = 0; j < 2; j++) {
        const int r = rr + 64 * j;
#pragma unroll
        for (int i = 0; i < 4; i++) {
            const int kc = cc + i * 8;
            float4 v0 = *(const float4*)(Qb + (size_t)r * D_MODEL + kc);
            float4 v1 = *(const float4*)(Qb + (size_t)r * D_MODEL + kc + 4);
            float vv[8] = {v0.x, v0.y, v0.z, v0.w, v1.x, v1.y, v1.z, v1.w};
#pragma unroll
            for (int c4 = 0; c4 < 8; c4++)
                Qs[(kc + c4) * 128 + (r ^ ((c4 & 3) << 3))] = f2tf(vv[c4]);
        }
    }

    float acc[2][8][4];
    float mi[2][2], li[2][2];
#pragma unroll
    for (int mt = 0; mt < 2; mt++) {
#pragma unroll
        for (int rh = 0; rh < 2; rh++) { mi[mt][rh] = -1e30f; li[mt][rh] = 0.0f; }
#pragma unroll
        for (int nt = 0; nt < 8; nt++)
#pragma unroll
            for (int i = 0; i < 4; i++) acc[mt][nt][i] = 0.0f;
    }

    __syncthreads();

    for (int kt = 0; kt < SEQ; kt += 64) {
        // Load K (k-major) and V (n-major) tiles
#pragma unroll
        for (int i = 0; i < 4; i++) {
            const int kc = cc + i * 8;
            float4 ka = *(const float4*)(Kb + (size_t)(kt + rr) * D_MODEL + kc);
            float4 kb2 = *(const float4*)(Kb + (size_t)(kt + rr) * D_MODEL + kc + 4);
            float kv[8] = {ka.x, ka.y, ka.z, ka.w, kb2.x, kb2.y, kb2.z, kb2.w};
            float4 va = *(const float4*)(Vb + (size_t)(kt + rr) * D_MODEL + kc);
            float4 vb2 = *(const float4*)(Vb + (size_t)(kt + rr) * D_MODEL + kc + 4);
            float vv[8] = {va.x, va.y, va.z, va.w, vb2.x, vb2.y, vb2.z, vb2.w};
#pragma unroll
            for (int c4 = 0; c4 < 8; c4++) {
                Ks[(kc + c4) * 64 + (rr ^ ((c4 & 3) << 3))] = f2tf(kv[c4]);
                Vs[rr * 64 + ((kc + c4) ^ ((rr & 3) << 3))] = f2tf(vv[c4]);
            }
        }
        __syncthreads();

        // S = Q @ K^T
        float s[2][8][4];
#pragma unroll
        for (int mt = 0; mt < 2; mt++)
#pragma unroll
            for (int nt = 0; nt < 8; nt++)
#pragma unroll
                for (int i = 0; i < 4; i++) s[mt][nt][i] = 0.0f;

#pragma unroll
        for (int ks = 0; ks < 8; ks++) {
            const int kb = ks * 8;
            uint32_t af[2][4], bf[8][2];
#pragma unroll
            for (int mt = 0; mt < 2; mt++) {
                const int m0 = warp * 32 + mt * 16;
                af[mt][0] = Qs[(kb + tk) * 128 + ((m0 + tm) ^ (tk << 3))];
                af[mt][1] = Qs[(kb + tk) * 128 + ((m0 + tm + 8) ^ (tk << 3))];
                af[mt][2] = Qs[(kb + tk + 4) * 128 + ((m0 + tm) ^ (tk << 3))];
                af[mt][3] = Qs[(kb + tk + 4) * 128 + ((m0 + tm + 8) ^ (tk << 3))];
            }
#pragma unroll
            for (int nt = 0; nt < 8; nt++) {
                const int n0 = nt * 8;
                bf[nt][0] = Ks[(kb + tk) * 64 + ((n0 + tm) ^ (tk << 3))];
                bf[nt][1] = Ks[(kb + tk + 4) * 64 + ((n0 + tm) ^ (tk << 3))];
            }
#pragma unroll
            for (int mt = 0; mt < 2; mt++)
#pragma unroll
                for (int nt = 0; nt < 8; nt++)
                    mma_m16n8k8(s[mt][nt], af[mt], bf[nt], s[mt][nt]);
        }

        // Online softmax (rows split across 4-lane quads)
#pragma unroll
        for (int mt = 0; mt < 2; mt++) {
#pragma unroll
            for (int rh = 0; rh < 2; rh++) {
                float mx = -1e30f;
#pragma unroll
                for (int nt = 0; nt < 8; nt++)
#pragma unroll
                    for (int j = 0; j < 2; j++) {
                        float v = s[mt][nt][rh * 2 + j] * 0.125f;
                        s[mt][nt][rh * 2 + j] = v;
                        mx = fmaxf(mx, v);
                    }
                mx = fmaxf(mx, __shfl_xor_sync(0xffffffffu, mx, 1));
                mx = fmaxf(mx, __shfl_xor_sync(0xffffffffu, mx, 2));
                const float mn = fmaxf(mi[mt][rh], mx);
                const float corr = __expf(mi[mt][rh] - mn);
                mi[mt][rh] = mn;
                float sum = 0.0f;
#pragma unroll
                for (int nt = 0; nt < 8; nt++)
#pragma unroll
                    for (int j = 0; j < 2; j++) {
                        float p = __expf(s[mt][nt][rh * 2 + j] - mn);
                        s[mt][nt][rh * 2 + j] = p;
                        sum += p;
                    }
                sum += __shfl_xor_sync(0xffffffffu, sum, 1);
                sum += __shfl_xor_sync(0xffffffffu, sum, 2);
                li[mt][rh] = li[mt][rh] * corr + sum;
#pragma unroll
                for (int nt = 0; nt < 8; nt++)
#pragma unroll
                    for (int j = 0; j < 2; j++)
                        acc[mt][nt][rh * 2 + j] *= corr;
            }
        }

        // P -> smem (a-frag layout: [kseq][q])
#pragma unroll
        for (int mt = 0; mt < 2; mt++)
#pragma unroll
            for (int nt = 0; nt < 8; nt++)
#pragma unroll
                for (int rh = 0; rh < 2; rh++)
#pragma unroll
                    for (int j = 0; j < 2; j++) {
                        const int r = warp * 32 + mt * 16 + tm + rh * 8;
                        const int cN = nt * 8 + 2 * tk + j;
                        Ps[cN * 128 + (r ^ ((cN & 3) << 3))] =
                            f2tf(s[mt][nt][rh * 2 + j]);
                    }
        __syncwarp();

        // O += P @ V
#pragma unroll
        for (int ks = 0; ks < 8; ks++) {
            const int kb = ks * 8;
            uint32_t af[2][4], bf[8][2];
#pragma unroll
            for (int mt = 0; mt < 2; mt++) {
                const int m0 = warp * 32 + mt * 16;
                af[mt][0] = Ps[(kb + tk) * 128 + ((m0 + tm) ^ (tk << 3))];
                af[mt][1] = Ps[(kb + tk) * 128 + ((m0 + tm + 8) ^ (tk << 3))];
                af[mt][2] = Ps[(kb + tk + 4) * 128 + ((m0 + tm) ^ (tk << 3))];
                af[mt][3] = Ps[(kb + tk + 4) * 128 + ((m0 + tm + 8) ^ (tk << 3))];
            }
#pragma unroll
            for (int nt = 0; nt < 8; nt++) {
                const int n0 = nt * 8;
                bf[nt][0] = Vs[(kb + tk) * 64 + ((n0 + tm) ^ (tk << 3))];
                bf[nt][1] = Vs[(kb + tk + 4) * 64 + ((n0 + tm) ^ (tk << 3))];
            }
#pragma unroll
            for (int mt = 0; mt < 2; mt++)
#pragma unroll
                for (int nt = 0; nt < 8; nt++)
                    mma_m16n8k8(acc[mt][nt], af[mt], bf[nt], acc[mt][nt]);
        }
        __syncthreads();
    }

    // Epilogue
#pragma unroll
    for (int mt = 0; mt < 2; mt++)
#pragma unroll
        for (int rh = 0; rh < 2; rh++) {
            const float inv = 1.0f / li[mt][rh];
            const int row = q0 + warp * 32 + mt * 16 + tm + rh * 8;
            float* orow = Og + (size_t)(b * SEQ + row) * D_MODEL + h * HEAD_DIM;
#pragma unroll
            for (int nt = 0; nt < 8; nt++) {
                const int col = nt * 8 + 2 * tk;
                *(float2*)(orow + col) =
                    make_float2(acc[mt][nt][rh * 2] * inv,
                                acc[mt][nt][rh * 2 + 1] * inv);
            }
        }
}

// ---------------------------------------------------------------------------
extern "C" void kernel_launch(void* const* d_in, const int* in_sizes, int n_in,
                              void* d_out, int out_size)
{
    const float* x  = (const float*)d_in[0];
    const float* Wq = (const float*)d_in[1];
    const float* bq = (const float*)d_in[2];
    const float* Wk = (const float*)d_in[3];
    const float* bk = (const float*)d_in[4];
    const float* Wv = (const float*)d_in[5];
    const float* bv = (const float*)d_in[6];
    const float* Wo = (const float*)d_in[7];
    const float* bo = (const float*)d_in[8];
    float* out = (float*)d_out;

    float *Qd, *Kd, *Vd, *Od;
    cudaGetSymbolAddress((void**)&Qd, g_Q);
    cudaGetSymbolAddress((void**)&Kd, g_K);
    cudaGetSymbolAddress((void**)&Vd, g_V);
    cudaGetSymbolAddress((void**)&Od, g_O);

    cudaFuncSetAttribute(flash_tf32, cudaFuncAttributeMaxDynamicSharedMemorySize,
                         98304);

    dim3 gemm_grid(D_MODEL / 128, MTOT / 128);  // (8, 32)
    gemm_tf32<<<gemm_grid, 256>>>(x, Wq, bq, Qd);
    gemm_tf32<<<gemm_grid, 256>>>(x, Wk, bk, Kd);
    gemm_tf32<<<gemm_grid, 256>>>(x, Wv, bv, Vd);

    dim3 attn_grid(SEQ / 128, BATCH * NUM_HEAD);  // (16, 32)
    flash_tf32<<<attn_grid, 128, 98304>>>(Qd, Kd, Vd, Od);

    gemm_tf32<<<gemm_grid, 256>>>(Od, Wo, bo, out);
}

// round 4
// speedup vs baseline: 2.4530x; 1.2245x over previous
#include <cuda_runtime.h>
#include <stdint.h>

#define D_MODEL 1024
#define NUM_HEAD 16
#define HEAD_DIM 64
#define BATCH 2
#define SEQ 2048
#define MTOT 4096

__device__ float g_Q[(size_t)MTOT * D_MODEL];
__device__ float g_K[(size_t)MTOT * D_MODEL];
__device__ float g_V[(size_t)MTOT * D_MODEL];
__device__ float g_O[(size_t)MTOT * D_MODEL];

__device__ __forceinline__ uint32_t f2tf(float x) {
    uint32_t r;
    asm("cvt.rna.tf32.f32 %0, %1;" : "=r"(r) : "f"(x));
    return r;
}

// Round raw fp32 bits to tf32 (nearest, half-away): MMA ignores low 13 bits,
// so biasing the magnitude by 0x1000 implements the rounding.
__device__ __forceinline__ uint32_t rnd(uint32_t u) { return u + 0x1000u; }

__device__ __forceinline__ void mma_m16n8k8(float d[4], const uint32_t a[4],
                                            const uint32_t b[2], const float c[4]) {
    asm volatile(
        "mma.sync.aligned.m16n8k8.row.col.f32.tf32.tf32.f32 "
        "{%0,%1,%2,%3}, {%4,%5,%6,%7}, {%8,%9}, {%10,%11,%12,%13};\n"
        : "=f"(d[0]), "=f"(d[1]), "=f"(d[2]), "=f"(d[3])
        : "r"(a[0]), "r"(a[1]), "r"(a[2]), "r"(a[3]),
          "r"(b[0]), "r"(b[1]),
          "f"(c[0]), "f"(c[1]), "f"(c[2]), "f"(c[3]));
}

__device__ __forceinline__ uint32_t s2u(const void* p) {
    return (uint32_t)__cvta_generic_to_shared(p);
}
__device__ __forceinline__ void cp16(uint32_t s, const void* g) {
    asm volatile("cp.async.cg.shared.global [%0], [%1], 16;" :: "r"(s), "l"(g));
}
__device__ __forceinline__ void cpcommit() {
    asm volatile("cp.async.commit_group;");
}
template <int N> __device__ __forceinline__ void cpwait() {
    asm volatile("cp.async.wait_group %0;" :: "n"(N));
}

// ---------------------------------------------------------------------------
// GEMM (NT): C[M,N] = A @ W^T + bias. 128x128x16 tiles, 4-stage cp.async.
// Smem stage: A[128][20] + B[128][20] floats (pad-20: conflict-free frags).
// gridDim.z selects (W,bias,C) for fused QKV.
// ---------------------------------------------------------------------------
#define GSTAGE 4
#define GSTW 5120  // floats per stage (2 * 128*20)

__global__ __launch_bounds__(256) void gemm_tf32(
    const float* __restrict__ A,
    const float* __restrict__ W0, const float* __restrict__ W1,
    const float* __restrict__ W2,
    const float* __restrict__ b0p, const float* __restrict__ b1p,
    const float* __restrict__ b2p,
    float* __restrict__ C0, float* __restrict__ C1, float* __restrict__ C2)
{
    extern __shared__ float sm[];
    const int z = blockIdx.z;
    const float* W = (z == 0) ? W0 : (z == 1) ? W1 : W2;
    const float* bias = (z == 0) ? b0p : (z == 1) ? b1p : b2p;
    float* C = (z == 0) ? C0 : (z == 1) ? C1 : C2;

    const int tid = threadIdx.x;
    const int warp = tid >> 5, lane = tid & 31;
    const int wm = warp >> 1, wn = warp & 1;
    const int tm = lane >> 2, tk = lane & 3;

    const float* Ab = A + (size_t)(blockIdx.y * 128) * D_MODEL;
    const float* Wb = W + (size_t)(blockIdx.x * 128) * D_MODEL;

    const int lrow = tid >> 1;         // 0..127
    const int lk = (tid & 1) * 8;      // 0 or 8

    float acc[2][8][4];
#pragma unroll
    for (int mt = 0; mt < 2; mt++)
#pragma unroll
        for (int nt = 0; nt < 8; nt++)
#pragma unroll
            for (int i = 0; i < 4; i++) acc[mt][nt][i] = 0.0f;

#pragma unroll
    for (int s = 0; s < GSTAGE - 1; s++) {
        float* SA = sm + s * GSTW;
        float* SB = SA + 2560;
        uint32_t sa = s2u(SA + lrow * 20 + lk);
        uint32_t sb = s2u(SB + lrow * 20 + lk);
        const float* ga = Ab + (size_t)lrow * D_MODEL + s * 16 + lk;
        const float* gw = Wb + (size_t)lrow * D_MODEL + s * 16 + lk;
        cp16(sa, ga); cp16(sa + 16, ga + 4);
        cp16(sb, gw); cp16(sb + 16, gw + 4);
        cpcommit();
    }

    const int NIT = D_MODEL / 16;  // 64
    for (int it = 0; it < NIT; it++) {
        cpwait<GSTAGE - 2>();
        __syncthreads();

        const int ns = it + GSTAGE - 1;
        if (ns < NIT) {
            float* SA = sm + (ns & (GSTAGE - 1)) * GSTW;
            float* SB = SA + 2560;
            uint32_t sa = s2u(SA + lrow * 20 + lk);
            uint32_t sb = s2u(SB + lrow * 20 + lk);
            const float* ga = Ab + (size_t)lrow * D_MODEL + ns * 16 + lk;
            const float* gw = Wb + (size_t)lrow * D_MODEL + ns * 16 + lk;
            cp16(sa, ga); cp16(sa + 16, ga + 4);
            cp16(sb, gw); cp16(sb + 16, gw + 4);
        }
        cpcommit();

        const uint32_t* UA = (const uint32_t*)(sm + (it & (GSTAGE - 1)) * GSTW);
        const uint32_t* UB = UA + 2560;

#pragma unroll
        for (int ks = 0; ks < 2; ks++) {
            const int kb = ks * 8;
            uint32_t af[2][4], bf[8][2];
#pragma unroll
            for (int mt = 0; mt < 2; mt++) {
                const int m0 = wm * 32 + mt * 16;
                af[mt][0] = rnd(UA[(m0 + tm) * 20 + kb + tk]);
                af[mt][1] = rnd(UA[(m0 + tm + 8) * 20 + kb + tk]);
                af[mt][2] = rnd(UA[(m0 + tm) * 20 + kb + tk + 4]);
                af[mt][3] = rnd(UA[(m0 + tm + 8) * 20 + kb + tk + 4]);
            }
#pragma unroll
            for (int nt = 0; nt < 8; nt++) {
                const int n0 = wn * 64 + nt * 8;
                bf[nt][0] = rnd(UB[(n0 + tm) * 20 + kb + tk]);
                bf[nt][1] = rnd(UB[(n0 + tm) * 20 + kb + tk + 4]);
            }
#pragma unroll
            for (int mt = 0; mt < 2; mt++)
#pragma unroll
                for (int nt = 0; nt < 8; nt++)
                    mma_m16n8k8(acc[mt][nt], af[mt], bf[nt], acc[mt][nt]);
        }
    }

#pragma unroll
    for (int mt = 0; mt < 2; mt++) {
        const int r0 = blockIdx.y * 128 + wm * 32 + mt * 16 + tm;
#pragma unroll
        for (int nt = 0; nt < 8; nt++) {
            const int col = blockIdx.x * 128 + wn * 64 + nt * 8 + 2 * tk;
            const float bb0 = bias[col], bb1 = bias[col + 1];
            *(float2*)(C + (size_t)r0 * D_MODEL + col) =
                make_float2(acc[mt][nt][0] + bb0, acc[mt][nt][1] + bb1);
            *(float2*)(C + (size_t)(r0 + 8) * D_MODEL + col) =
                make_float2(acc[mt][nt][2] + bb0, acc[mt][nt][3] + bb1);
        }
    }
}

// ---------------------------------------------------------------------------
// Flash attention: 4 warps, BQ=64 (16 rows/warp), BKT=64,
// 2-stage cp.async K/V. Smem (floats):
//   Qs 0..4095 (tf32-rna, swizzled [k][m])   Ps 4096..8191 (tf32-rna, swizzled)
//   K stages at 8192 + st*4352  ([n][k] pad 68, raw f32 -> rnd at frag load)
//   V stages at 16896 + st*4608 ([k][n] pad 72, raw f32 -> rnd at frag load)
// ---------------------------------------------------------------------------
__global__ __launch_bounds__(128) void flash_tf32(
    const float* __restrict__ Qg, const float* __restrict__ Kg,
    const float* __restrict__ Vg, float* __restrict__ Og)
{
    extern __shared__ float sm[];
    uint32_t* QsU = (uint32_t*)sm;
    uint32_t* PsU = (uint32_t*)(sm + 4096);
    float* Kbase = sm + 8192;
    float* Vbase = sm + 16896;

    const int tid = threadIdx.x;
    const int warp = tid >> 5, lane = tid & 31;
    const int tm = lane >> 2, tk = lane & 3;
    const int b = blockIdx.y >> 4, h = blockIdx.y & 15;
    const int q0 = blockIdx.x * 64;

    const float* Qb = Qg + (size_t)(b * SEQ + q0) * D_MODEL + h * HEAD_DIM;
    const float* Kb = Kg + (size_t)(b * SEQ) * D_MODEL + h * HEAD_DIM;
    const float* Vb = Vg + (size_t)(b * SEQ) * D_MODEL + h * HEAD_DIM;

    // ---- load Q (once), fold scale 1/8, cvt.rna, swizzled [k][m] store ----
    const int qr = tid & 63;          // row 0..63
    const int qh = (tid >> 6) * 32;   // col half
#pragma unroll
    for (int i = 0; i < 4; i++) {
        const int kc = qh + i * 8;
        float4 v0 = *(const float4*)(Qb + (size_t)qr * D_MODEL + kc);
        float4 v1 = *(const float4*)(Qb + (size_t)qr * D_MODEL + kc + 4);
        float vv[8] = {v0.x, v0.y, v0.z, v0.w, v1.x, v1.y, v1.z, v1.w};
#pragma unroll
        for (int c4 = 0; c4 < 8; c4++) {
            const int k = kc + c4;
            QsU[k * 64 + (qr ^ ((k & 3) << 3))] = f2tf(vv[c4] * 0.125f);
        }
    }

    const int kr = tid & 63;
    const int kh = (tid >> 6) * 32;

    {
        uint32_t sk = s2u(Kbase + kr * 68 + kh);
        uint32_t sv = s2u(Vbase + kr * 72 + kh);
        const float* gk = Kb + (size_t)kr * D_MODEL + kh;
        const float* gv = Vb + (size_t)kr * D_MODEL + kh;
#pragma unroll
        for (int i = 0; i < 8; i++) {
            cp16(sk + i * 16, gk + i * 4);
            cp16(sv + i * 16, gv + i * 4);
        }
        cpcommit();
    }

    float s[8][4], acc[8][4], mi[2], li[2];
#pragma unroll
    for (int nt = 0; nt < 8; nt++)
#pragma unroll
        for (int i = 0; i < 4; i++) acc[nt][i] = 0.0f;
    mi[0] = mi[1] = -1e30f;
    li[0] = li[1] = 0.0f;

    const int m0 = warp * 16;
    const int NKT = SEQ / 64;  // 32

    for (int it = 0; it < NKT; it++) {
        cpwait<0>();
        __syncthreads();

        if (it + 1 < NKT) {
            const int st = (it + 1) & 1;
            uint32_t sk = s2u(Kbase + st * 4352 + kr * 68 + kh);
            uint32_t sv = s2u(Vbase + st * 4608 + kr * 72 + kh);
            const float* gk = Kb + (size_t)((it + 1) * 64 + kr) * D_MODEL + kh;
            const float* gv = Vb + (size_t)((it + 1) * 64 + kr) * D_MODEL + kh;
#pragma unroll
            for (int i = 0; i < 8; i++) {
                cp16(sk + i * 16, gk + i * 4);
                cp16(sv + i * 16, gv + i * 4);
            }
        }
        cpcommit();

        const uint32_t* KU = (const uint32_t*)(Kbase + (it & 1) * 4352);
        const uint32_t* VU = (const uint32_t*)(Vbase + (it & 1) * 4608);

        // ---- S = Q @ K^T ----
#pragma unroll
        for (int nt = 0; nt < 8; nt++)
#pragma unroll
            for (int i = 0; i < 4; i++) s[nt][i] = 0.0f;

#pragma unroll
        for (int ks = 0; ks < 8; ks++) {
            const int kb = ks * 8;
            uint32_t af[4], bf[8][2];
            af[0] = QsU[(kb + tk) * 64 + ((m0 + tm) ^ (tk << 3))];
            af[1] = QsU[(kb + tk) * 64 + ((m0 + tm + 8) ^ (tk << 3))];
            af[2] = QsU[(kb + tk + 4) * 64 + ((m0 + tm) ^ (tk << 3))];
            af[3] = QsU[(kb + tk + 4) * 64 + ((m0 + tm + 8) ^ (tk << 3))];
#pragma unroll
            for (int nt = 0; nt < 8; nt++) {
                const int n0 = nt * 8;
                bf[nt][0] = rnd(KU[(n0 + tm) * 68 + kb + tk]);
                bf[nt][1] = rnd(KU[(n0 + tm) * 68 + kb + tk + 4]);
            }
#pragma unroll
            for (int nt = 0; nt < 8; nt++)
                mma_m16n8k8(s[nt], af, bf[nt], s[nt]);
        }

        // ---- online softmax (scale folded into Q) ----
#pragma unroll
        for (int rh = 0; rh < 2; rh++) {
            float mx = -1e30f;
#pragma unroll
            for (int nt = 0; nt < 8; nt++)
#pragma unroll
                for (int j = 0; j < 2; j++)
                    mx = fmaxf(mx, s[nt][rh * 2 + j]);
            mx = fmaxf(mx, __shfl_xor_sync(0xffffffffu, mx, 1));
            mx = fmaxf(mx, __shfl_xor_sync(0xffffffffu, mx, 2));
            const float mn = fmaxf(mi[rh], mx);
            const float corr = __expf(mi[rh] - mn);
            mi[rh] = mn;
            float sum = 0.0f;
#pragma unroll
            for (int nt = 0; nt < 8; nt++)
#pragma unroll
                for (int j = 0; j < 2; j++) {
                    float p = __expf(s[nt][rh * 2 + j] - mn);
                    s[nt][rh * 2 + j] = p;
                    sum += p;
                }
            sum += __shfl_xor_sync(0xffffffffu, sum, 1);
            sum += __shfl_xor_sync(0xffffffffu, sum, 2);
            li[rh] = li[rh] * corr + sum;
#pragma unroll
            for (int nt = 0; nt < 8; nt++)
#pragma unroll
                for (int j = 0; j < 2; j++)
                    acc[nt][rh * 2 + j] *= corr;
        }

        // ---- P -> smem (a-frag layout [k][m], swizzled, rna) ----
#pragma unroll
        for (int nt = 0; nt < 8; nt++)
#pragma unroll
            for (int rh = 0; rh < 2; rh++)
#pragma unroll
                for (int j = 0; j < 2; j++) {
                    const int r = m0 + tm + rh * 8;
                    const int cN = nt * 8 + 2 * tk + j;
                    PsU[cN * 64 + (r ^ ((cN & 3) << 3))] = f2tf(s[nt][rh * 2 + j]);
                }
        __syncwarp();

        // ---- O += P @ V ----
#pragma unroll
        for (int ks = 0; ks < 8; ks++) {
            const int kb = ks * 8;
            uint32_t af[4], bf[8][2];
            af[0] = PsU[(kb + tk) * 64 + ((m0 + tm) ^ (tk << 3))];
            af[1] = PsU[(kb + tk) * 64 + ((m0 + tm + 8) ^ (tk << 3))];
            af[2] = PsU[(kb + tk + 4) * 64 + ((m0 + tm) ^ (tk << 3))];
            af[3] = PsU[(kb + tk + 4) * 64 + ((m0 + tm + 8) ^ (tk << 3))];
#pragma unroll
            for (int nt = 0; nt < 8; nt++) {
                const int n0 = nt * 8;
                bf[nt][0] = rnd(VU[(kb + tk) * 72 + n0 + tm]);
                bf[nt][1] = rnd(VU[(kb + tk + 4) * 72 + n0 + tm]);
            }
#pragma unroll
            for (int nt = 0; nt < 8; nt++)
                mma_m16n8k8(acc[nt], af, bf[nt], acc[nt]);
        }
    }

    // ---- epilogue ----
#pragma unroll
    for (int rh = 0; rh < 2; rh++) {
        const float inv = 1.0f / li[rh];
        const int row = q0 + m0 + tm + rh * 8;
        float* orow = Og + (size_t)(b * SEQ + row) * D_MODEL + h * HEAD_DIM;
#pragma unroll
        for (int nt = 0; nt < 8; nt++) {
            const int col = nt * 8 + 2 * tk;
            *(float2*)(orow + col) =
                make_float2(acc[nt][rh * 2] * inv, acc[nt][rh * 2 + 1] * inv);
        }
    }
}

// ---------------------------------------------------------------------------
extern "C" void kernel_launch(void* const* d_in, const int* in_sizes, int n_in,
                              void* d_out, int out_size)
{
    const float* x  = (const float*)d_in[0];
    const float* Wq = (const float*)d_in[1];
    const float* bq = (const float*)d_in[2];
    const float* Wk = (const float*)d_in[3];
    const float* bk = (const float*)d_in[4];
    const float* Wv = (const float*)d_in[5];
    const float* bv = (const float*)d_in[6];
    const float* Wo = (const float*)d_in[7];
    const float* bo = (const float*)d_in[8];
    float* out = (float*)d_out;

    float *Qd, *Kd, *Vd, *Od;
    cudaGetSymbolAddress((void**)&Qd, g_Q);
    cudaGetSymbolAddress((void**)&Kd, g_K);
    cudaGetSymbolAddress((void**)&Vd, g_V);
    cudaGetSymbolAddress((void**)&Od, g_O);

    static int init = 0;
    if (!init) {
        cudaFuncSetAttribute(gemm_tf32,
                             cudaFuncAttributeMaxDynamicSharedMemorySize, 81920);
        cudaFuncSetAttribute(flash_tf32,
                             cudaFuncAttributeMaxDynamicSharedMemorySize, 104448);
        init = 1;
    }

    dim3 qkv_grid(D_MODEL / 128, MTOT / 128, 3);  // (8, 32, 3)
    gemm_tf32<<<qkv_grid, 256, 81920>>>(x, Wq, Wk, Wv, bq, bk, bv, Qd, Kd, Vd);

    dim3 attn_grid(SEQ / 64, BATCH * NUM_HEAD);  // (32, 32)
    flash_tf32<<<attn_grid, 128, 104448>>>(Qd, Kd, Vd, Od);

    dim3 o_grid(D_MODEL / 128, MTOT / 128, 1);
    gemm_tf32<<<o_grid, 256, 81920>>>(Od, Wo, Wo, Wo, bo, bo, bo, out, out, out);
}